// round 17
// baseline (speedup 1.0000x reference)
#include <cuda_runtime.h>
#include <cuda_fp16.h>
#include <math.h>
#include <stdint.h>

#define NN 100000
#define DD 128
#define NE 1600000

#define MLP_THREADS 256          // 8 warps; each warp owns 16 rows
#define ROWS_PER_BLOCK 128
#define N_CHUNKS 24              // 12 layer-0 (384 k) + 12 inner (3 x 128 k)
#define HS16 68                  // H slab row stride in uint32 (half2) units
#define BUCKET 64                // fixed per-node edge-bucket capacity

// prep_kernel block ranges: fill first (latency-bound, start early),
// then xconv / wfrag (bandwidth-bound, overlap the fill atomics).
#define PREP_FILL_BLOCKS  1563   // ceil(NE/4/256)
#define PREP_XCONV_BLOCKS 12500  // NN*128/4 float4s / 256 threads
#define PREP_WFRAG_BLOCKS 48     // N_CHUNKS*512/256
#define PREP_BLOCKS (PREP_FILL_BLOCKS + PREP_XCONV_BLOCKS + PREP_WFRAG_BLOCKS)

// Scratch (allocation-free rule: __device__ globals)
__device__ uint32_t g_xh[(size_t)NN * 64];    // x as half2 pairs (plain layout)
__device__ uint32_t g_mih[(size_t)NN * 64];
__device__ uint32_t g_moh[(size_t)NN * 64];

__device__ int   g_cnt[2 * NN];               // per-(node,dir) degree/cursor
__device__ int2  g_lst_in[(size_t)NN * BUCKET];    // {src, w-bits} bucket per dst
__device__ int2  g_lst_out[(size_t)NN * BUCKET];   // {dst, w-bits} bucket per src
__device__ uint4 g_wfrag[N_CHUNKS * 2 * 8 * 32];   // fp16 frag-major weights

// ---------------------------------------------------------------------------
__device__ __forceinline__ float fast_tanh(float x) {
    float ax = fabsf(x);
    float t = __expf(-2.f * ax);
    float r = (1.f - t) * __frcp_rn(1.f + t);
    return copysignf(r, x);
}

__device__ __forceinline__ uint32_t pack_h2(float a, float b) {
    __half2 h = __floats2half2_rn(a, b);
    return *(uint32_t*)&h;
}

// ---------------------------------------------------------------------------
// Fused prep: direct-bucket fill (4 edges/thread, blocks [0,1563)),
// xconv (next 12500), wfrag (last 48).
// ---------------------------------------------------------------------------
__global__ void prep_kernel(const float* __restrict__ x, uint32_t* __restrict__ xh,
                            const float* __restrict__ W0, const float* __restrict__ W,
                            uint4* __restrict__ WF,
                            const int* __restrict__ ei, const float* __restrict__ e,
                            int* __restrict__ cnt,
                            int2* __restrict__ lin, int2* __restrict__ lout) {
    int b = blockIdx.x;
    if (b < PREP_FILL_BLOCKS) {
        // Direct bucket fill: 4 edges/thread (low reg pressure)
        int i = b * 256 + threadIdx.x;
        if (i >= NE / 4) return;
        int4 s = __ldg((const int4*)ei + i);
        int4 t = __ldg((const int4*)(ei + NE) + i);
        float4 w = __ldg((const float4*)e + i);
        int ss[4] = {s.x, s.y, s.z, s.w};
        int tt[4] = {t.x, t.y, t.z, t.w};
        float ww[4] = {w.x, w.y, w.z, w.w};
        int pin[4], pout[4];
#pragma unroll
        for (int u = 0; u < 4; u++) pin[u] = atomicAdd(&cnt[tt[u]], 1);
#pragma unroll
        for (int u = 0; u < 4; u++) pout[u] = atomicAdd(&cnt[NN + ss[u]], 1);
#pragma unroll
        for (int u = 0; u < 4; u++)
            lin[(size_t)tt[u] * BUCKET + pin[u]] = make_int2(ss[u], __float_as_int(ww[u]));
#pragma unroll
        for (int u = 0; u < 4; u++)
            lout[(size_t)ss[u] * BUCKET + pout[u]] = make_int2(tt[u], __float_as_int(ww[u]));
        return;
    }
    b -= PREP_FILL_BLOCKS;
    if (b < PREP_XCONV_BLOCKS) {
        int i = b * 256 + threadIdx.x;
        float4 v = __ldg((const float4*)x + i);
        uint2 o;
        o.x = pack_h2(v.x, v.y);
        o.y = pack_h2(v.z, v.w);
        ((uint2*)xh)[i] = o;
        return;
    }
    b -= PREP_XCONV_BLOCKS;
    {
        int idx = b * 256 + threadIdx.x;
        int lane = idx & 31;
        int q = (idx >> 5) & 7;
        int s = (idx >> 8) & 1;
        int chunk = idx >> 9;
        int t4 = lane & 3, g = lane >> 2;

        const float* Wsrc;
        int kbase;
        if (chunk < 12) {
            Wsrc = W0;
            kbase = chunk * 32;
        } else {
            int c2 = chunk - 12;
            Wsrc = W + (size_t)(c2 >> 2) * 128 * 128;
            kbase = (c2 & 3) * 32;
        }
        int k0 = kbase + s * 16 + 2 * t4;
        int n0 = (2 * q) * 8 + g;
        int n1 = n0 + 8;

        uint4 o;
        o.x = pack_h2(__ldg(&Wsrc[(size_t)k0 * 128 + n0]),       __ldg(&Wsrc[(size_t)(k0 + 1) * 128 + n0]));
        o.y = pack_h2(__ldg(&Wsrc[(size_t)(k0 + 8) * 128 + n0]), __ldg(&Wsrc[(size_t)(k0 + 9) * 128 + n0]));
        o.z = pack_h2(__ldg(&Wsrc[(size_t)k0 * 128 + n1]),       __ldg(&Wsrc[(size_t)(k0 + 1) * 128 + n1]));
        o.w = pack_h2(__ldg(&Wsrc[(size_t)(k0 + 8) * 128 + n1]), __ldg(&Wsrc[(size_t)(k0 + 9) * 128 + n1]));
        WF[idx] = o;
    }
}

// ---------------------------------------------------------------------------
// Gather (fp16): one warp per (node, dir). Buckets at node*BUCKET.
// Edge-list entries loaded PAIRED as int4 (2 edges per LDG.128).
// ---------------------------------------------------------------------------
__global__ __launch_bounds__(256) void gather_kernel(
    const uint32_t* __restrict__ xh, const int* __restrict__ cnt,
    const int2* __restrict__ lin, const int2* __restrict__ lout,
    uint32_t* __restrict__ mih, uint32_t* __restrict__ moh) {
    int wg = (blockIdx.x * blockDim.x + threadIdx.x) >> 5;
    int lane = threadIdx.x & 31;
    if (wg >= 2 * NN) return;

    const int2* lst;
    uint32_t* dst;
    int node;
    if (wg < NN) { node = wg; lst = lin; dst = mih; }
    else         { node = wg - NN; lst = lout; dst = moh; }

    int beg = node * BUCKET;
    int end = beg + cnt[wg];

    float2 acc0 = make_float2(0.f, 0.f);
    float2 acc1 = make_float2(0.f, 0.f);

    int j = beg;
    for (; j + 8 <= end; j += 8) {
        int4 pp[4];
#pragma unroll
        for (int u = 0; u < 4; u++)
            pp[u] = __ldg((const int4*)(lst + j) + u);   // 2 edges per load
        uint2 v[8];
#pragma unroll
        for (int u = 0; u < 4; u++) {
            v[2 * u]     = __ldg((const uint2*)(xh + (size_t)pp[u].x * 64) + lane);
            v[2 * u + 1] = __ldg((const uint2*)(xh + (size_t)pp[u].z * 64) + lane);
        }
#pragma unroll
        for (int u = 0; u < 4; u++) {
            float w0 = __int_as_float(pp[u].y);
            float w1 = __int_as_float(pp[u].w);
            float2 f;
            f = __half22float2(*(__half2*)&v[2 * u].x);
            acc0.x = fmaf(w0, f.x, acc0.x); acc0.y = fmaf(w0, f.y, acc0.y);
            f = __half22float2(*(__half2*)&v[2 * u].y);
            acc1.x = fmaf(w0, f.x, acc1.x); acc1.y = fmaf(w0, f.y, acc1.y);
            f = __half22float2(*(__half2*)&v[2 * u + 1].x);
            acc0.x = fmaf(w1, f.x, acc0.x); acc0.y = fmaf(w1, f.y, acc0.y);
            f = __half22float2(*(__half2*)&v[2 * u + 1].y);
            acc1.x = fmaf(w1, f.x, acc1.x); acc1.y = fmaf(w1, f.y, acc1.y);
        }
    }
    for (; j < end; j++) {
        int2 p0 = __ldg(&lst[j]);
        uint2 v0 = __ldg((const uint2*)(xh + (size_t)p0.x * 64) + lane);
        float w = __int_as_float(p0.y);
        float2 f0 = __half22float2(*(__half2*)&v0.x);
        float2 f1 = __half22float2(*(__half2*)&v0.y);
        acc0.x = fmaf(w, f0.x, acc0.x); acc0.y = fmaf(w, f0.y, acc0.y);
        acc1.x = fmaf(w, f1.x, acc1.x); acc1.y = fmaf(w, f1.y, acc1.y);
    }

    uint2 o;
    o.x = pack_h2(acc0.x, acc0.y);
    o.y = pack_h2(acc1.x, acc1.y);
    ((uint2*)(dst + (size_t)node * 64))[lane] = o;
}

// ---------------------------------------------------------------------------
// Fused 4-layer MLP, fp16 m16n8k16. 16 rows per warp, 16 warps/SM. (Champion.)
// ---------------------------------------------------------------------------
#define MMA16(cj, A0r, A1r, A2r, A3r, B0r, B1r)                                  \
    asm volatile(                                                                \
        "mma.sync.aligned.m16n8k16.row.col.f32.f16.f16.f32 "                     \
        "{%0,%1,%2,%3}, {%4,%5,%6,%7}, {%8,%9}, {%0,%1,%2,%3};"                  \
        : "+f"(cj[0]), "+f"(cj[1]), "+f"(cj[2]), "+f"(cj[3])                     \
        : "r"(A0r), "r"(A1r), "r"(A2r), "r"(A3r), "r"(B0r), "r"(B1r))

__global__ __launch_bounds__(MLP_THREADS, 2) void mlp_fused(
    const uint32_t* __restrict__ A0h, const uint32_t* __restrict__ A1h,
    const uint32_t* __restrict__ A2h,
    const uint4* __restrict__ WF,
    const float* __restrict__ b0v, const float* __restrict__ g0v,
    const float* __restrict__ be0v,
    const float* __restrict__ bv, const float* __restrict__ gv,
    const float* __restrict__ bev,
    float* __restrict__ out)
{
    extern __shared__ uint32_t smem[];
    const int tid = threadIdx.x;
    const int lane = tid & 31;
    const int wid = tid >> 5;
    const int g = lane >> 2;
    const int t4 = lane & 3;
    const int row0 = blockIdx.x * ROWS_PER_BLOCK + wid * 16;

    uint32_t* Hw = smem + wid * 16 * HS16;   // per-warp slab [16][HS16] half2

    float c[16][4];
#pragma unroll
    for (int j = 0; j < 16; j++)
#pragma unroll
        for (int q = 0; q < 4; q++) c[j][q] = 0.f;

    int r00 = row0 + g;
    size_t cr00 = (size_t)(r00 < NN ? r00 : 0) * 64;
    size_t cr01 = (size_t)((r00 + 8) < NN ? (r00 + 8) : 0) * 64;

    // ---------------- Layer 0: K = 384 over {mih, moh, xh} ----------------
    const uint32_t* Ap[3] = {A0h, A1h, A2h};
#pragma unroll 1
    for (int m = 0; m < 3; m++) {
        const uint32_t* A = Ap[m];
#pragma unroll
        for (int kc = 0; kc < 4; kc++) {
            int chunk = m * 4 + kc;
#pragma unroll
            for (int s = 0; s < 2; s++) {
                int kidx = kc * 16 + s * 8 + t4;       // uint32 (half2) index
                uint32_t a0[4];
                a0[0] = __ldg(A + cr00 + kidx);
                a0[1] = __ldg(A + cr01 + kidx);
                a0[2] = __ldg(A + cr00 + kidx + 4);
                a0[3] = __ldg(A + cr01 + kidx + 4);
                const uint4* wfk = WF + ((size_t)(chunk * 2 + s) << 8);
#pragma unroll
                for (int q = 0; q < 8; q++) {
                    uint4 bb = __ldg(&wfk[(q << 5) + lane]);
                    MMA16(c[2 * q],     a0[0], a0[1], a0[2], a0[3], bb.x, bb.y);
                    MMA16(c[2 * q + 1], a0[0], a0[1], a0[2], a0[3], bb.z, bb.w);
                }
            }
        }
    }

    // ---------------- 4 epilogues + 3 inner layers ----------------
#pragma unroll 1
    for (int l = 0; l < 4; l++) {
        const float* bias  = (l == 0) ? b0v  : bv  + (l - 1) * 128;
        const float* gamma = (l == 0) ? g0v  : gv  + (l - 1) * 128;
        const float* beta  = (l == 0) ? be0v : bev + (l - 1) * 128;

        float s0 = 0.f, q0 = 0.f, s1 = 0.f, q1 = 0.f;
#pragma unroll
        for (int j = 0; j < 16; j++) {
            int col = j * 8 + 2 * t4;
            float2 bb = __ldg((const float2*)(bias + col));
            c[j][0] += bb.x; c[j][1] += bb.y;
            c[j][2] += bb.x; c[j][3] += bb.y;
            s0 += c[j][0] + c[j][1];
            q0 += c[j][0] * c[j][0] + c[j][1] * c[j][1];
            s1 += c[j][2] + c[j][3];
            q1 += c[j][2] * c[j][2] + c[j][3] * c[j][3];
        }
#pragma unroll
        for (int o = 1; o <= 2; o <<= 1) {
            s0 += __shfl_xor_sync(0xFFFFFFFFu, s0, o);
            q0 += __shfl_xor_sync(0xFFFFFFFFu, q0, o);
            s1 += __shfl_xor_sync(0xFFFFFFFFu, s1, o);
            q1 += __shfl_xor_sync(0xFFFFFFFFu, q1, o);
        }
        float mean0 = s0 * (1.f / 128.f);
        float rstd0 = rsqrtf(q0 * (1.f / 128.f) - mean0 * mean0 + 1e-5f);
        float mean1 = s1 * (1.f / 128.f);
        float rstd1 = rsqrtf(q1 * (1.f / 128.f) - mean1 * mean1 + 1e-5f);

        if (l == 3) {
            int ra = row0 + g;
            int rb = ra + 8;
#pragma unroll
            for (int j = 0; j < 16; j++) {
                int col = j * 8 + 2 * t4;
                float2 gg = __ldg((const float2*)(gamma + col));
                float2 ee = __ldg((const float2*)(beta + col));
                if (ra < NN) {
                    float2 o1;
                    o1.x = fast_tanh((c[j][0] - mean0) * rstd0 * gg.x + ee.x);
                    o1.y = fast_tanh((c[j][1] - mean0) * rstd0 * gg.y + ee.y);
                    *(float2*)(out + (size_t)ra * DD + col) = o1;
                }
                if (rb < NN) {
                    float2 o2;
                    o2.x = fast_tanh((c[j][2] - mean1) * rstd1 * gg.x + ee.x);
                    o2.y = fast_tanh((c[j][3] - mean1) * rstd1 * gg.y + ee.y);
                    *(float2*)(out + (size_t)rb * DD + col) = o2;
                }
            }
            break;
        }

        // Write h (half2) into per-warp smem slab.
        __syncwarp();
#pragma unroll
        for (int j = 0; j < 16; j++) {
            int col = j * 8 + 2 * t4;
            float2 gg = __ldg((const float2*)(gamma + col));
            float2 ee = __ldg((const float2*)(beta + col));
            int ci = j * 4 + t4;
            float h00 = fast_tanh((c[j][0] - mean0) * rstd0 * gg.x + ee.x);
            float h01 = fast_tanh((c[j][1] - mean0) * rstd0 * gg.y + ee.y);
            float h10 = fast_tanh((c[j][2] - mean1) * rstd1 * gg.x + ee.x);
            float h11 = fast_tanh((c[j][3] - mean1) * rstd1 * gg.y + ee.y);
            Hw[(g) * HS16 + ci]     = pack_h2(h00, h01);
            Hw[(g + 8) * HS16 + ci] = pack_h2(h10, h11);
            c[j][0] = 0.f; c[j][1] = 0.f;
            c[j][2] = 0.f; c[j][3] = 0.f;
        }
        __syncwarp();

        // Next layer GEMM: h (in Hw) @ W[l], K = 128
#pragma unroll
        for (int kc = 0; kc < 4; kc++) {
            int chunk = 12 + l * 4 + kc;
#pragma unroll
            for (int s = 0; s < 2; s++) {
                int kidx = kc * 16 + s * 8 + t4;
                uint32_t a0[4];
                a0[0] = Hw[(g) * HS16 + kidx];
                a0[1] = Hw[(g + 8) * HS16 + kidx];
                a0[2] = Hw[(g) * HS16 + kidx + 4];
                a0[3] = Hw[(g + 8) * HS16 + kidx + 4];
                const uint4* wfk = WF + ((size_t)(chunk * 2 + s) << 8);
#pragma unroll
                for (int q = 0; q < 8; q++) {
                    uint4 bb = __ldg(&wfk[(q << 5) + lane]);
                    MMA16(c[2 * q],     a0[0], a0[1], a0[2], a0[3], bb.x, bb.y);
                    MMA16(c[2 * q + 1], a0[0], a0[1], a0[2], a0[3], bb.z, bb.w);
                }
            }
        }
    }
}

// ---------------------------------------------------------------------------
extern "C" void kernel_launch(void* const* d_in, const int* in_sizes, int n_in,
                              void* d_out, int out_size) {
    const float* x   = (const float*)d_in[0];
    const float* e   = (const float*)d_in[1];
    const int*   ei  = (const int*)d_in[2];
    const float* W0  = (const float*)d_in[3];
    const float* b0  = (const float*)d_in[4];
    const float* g0  = (const float*)d_in[5];
    const float* be0 = (const float*)d_in[6];
    const float* W   = (const float*)d_in[7];
    const float* b   = (const float*)d_in[8];
    const float* g   = (const float*)d_in[9];
    const float* be  = (const float*)d_in[10];
    float* out = (float*)d_out;

    uint32_t *xh, *mih, *moh;
    int *cnt;
    int2 *lin, *lout;
    uint4* wf;
    cudaGetSymbolAddress((void**)&xh, g_xh);
    cudaGetSymbolAddress((void**)&mih, g_mih);
    cudaGetSymbolAddress((void**)&moh, g_moh);
    cudaGetSymbolAddress((void**)&cnt, g_cnt);
    cudaGetSymbolAddress((void**)&lin, g_lst_in);
    cudaGetSymbolAddress((void**)&lout, g_lst_out);
    cudaGetSymbolAddress((void**)&wf, g_wfrag);

    const int smem_bytes = 8 * 16 * HS16 * 4;   // 8 warps x 16 rows x 68 words
    cudaFuncSetAttribute(mlp_fused,
                         cudaFuncAttributeMaxDynamicSharedMemorySize,
                         smem_bytes);

    cudaMemsetAsync(cnt, 0, 2 * NN * sizeof(int));

    prep_kernel<<<PREP_BLOCKS, 256>>>(x, xh, W0, W, wf, ei, e, cnt, lin, lout);

    {
        long long warps = 2LL * NN;
        int blocks = (int)((warps * 32 + 255) / 256);
        gather_kernel<<<blocks, 256>>>(xh, cnt, lin, lout, mih, moh);
    }

    const int gblocks = (NN + ROWS_PER_BLOCK - 1) / ROWS_PER_BLOCK;  // 782
    mlp_fused<<<gblocks, MLP_THREADS, smem_bytes>>>(
        mih, moh, xh, wf, b0, g0, be0, b, g, be, out);
}